// round 13
// baseline (speedup 1.0000x reference)
#include <cuda_runtime.h>
#include <cuda_pipeline.h>
#include <math.h>
#include <float.h>

// MultiScaleDynamicFusionGate — GB300 sm_103a — R13 (= R12 + dest `+ lane` fix)
// Single fused kernel: 296 blocks single wave, group-aligned balanced
// partition (3-4 groups/warp), 3-stage cp.async pipeline with TWO 4KB chunks
// always in flight (covers the ~2.5K-cycle inline MLP blob), split MLP
// accumulator chains, running row pointers.
// R12's rel_err=1.4e-3 was ISSUE_NEXT writing all lanes to the same smem
// slots: the destination pointer had lost its `+ lane`.

#define L_DIM 1024
#define N_GROUPS 8192
#define GRID_A 296
#define WARPS_A (GRID_A * 8)    // 2368

extern __shared__ float stageA[];       // [8 warps][3 stages][1024 floats] = 96KB

__global__ __launch_bounds__(256) void msdfg_kernel(
    const float* __restrict__ a1, const float* __restrict__ a2,
    const float* __restrict__ W1, const float* __restrict__ b1,
    const float* __restrict__ W2, const float* __restrict__ b2,
    const float* __restrict__ W3, const float* __restrict__ b3,
    const float* __restrict__ sw, float* __restrict__ out)
{
    __shared__ __align__(16) float rs[8][64];   // [warp][localrow*8+stat]
    __shared__ float shW1T[3][8][32];    // [s][f][o]
    __shared__ float shB1[3][32];
    __shared__ float shW2T[3][32][16];   // [s][f][o]
    __shared__ float shB2[3][16];
    __shared__ float shW3[3][16];
    __shared__ float shB3[3];
    __shared__ float shSW[3];

    const int tid  = threadIdx.x;
    const int w    = tid >> 5;
    const int lane = tid & 31;

    // ---- One-time weight staging ----
    for (int idx = tid; idx < 768; idx += 256) {          // W1 [3][32][8]
        int s = idx >> 8, rem = idx & 255;
        shW1T[s][rem & 7][rem >> 3] = W1[idx];
    }
    for (int idx = tid; idx < 1536; idx += 256) {         // W2 [3][16][32]
        int s = idx >> 9, rem = idx & 511;
        shW2T[s][rem & 31][rem >> 5] = W2[idx];
    }
    if (tid < 96)                 ((float*)shB1)[tid] = b1[tid];
    else if (tid < 144)           ((float*)shB2)[tid - 96]  = b2[tid - 96];
    else if (tid < 192)           ((float*)shW3)[tid - 144] = W3[tid - 144];
    else if (tid < 195)           ((float*)shB3)[tid - 192] = b3[tid - 192];
    else if (tid >= 200 && tid < 203) shSW[tid - 200] = sw[tid - 200];
    __syncthreads();

    // ---- Softmax over scale_weights (registers, per warp) ----
    float w0, w1g, w2g;
    {
        float t0 = shSW[0], t1 = shSW[1], t2 = shSW[2];
        float m  = fmaxf(t0, fmaxf(t1, t2));
        float e0 = __expf(t0 - m), e1 = __expf(t1 - m), e2 = __expf(t2 - m);
        float inv = 1.0f / (e0 + e1 + e2);
        w0 = e0 * inv; w1g = e1 * inv; w2g = e2 * inv;   // ws=2, ws=4, ws=8
    }

    // ---- Group-aligned contiguous partition ----
    const long long gwid = (long long)blockIdx.x * 8 + w;  // 0..2367
    const int g0 = (int)(((long long)N_GROUPS * gwid)       / WARPS_A);
    const int g1 = (int)(((long long)N_GROUPS * (gwid + 1)) / WARPS_A);
    const int c0 = g0 * 16;             // first chunk (group-aligned, even)
    const int n  = (g1 - g0) * 16;      // 48 or 64 chunks

    float* stg = stageA + w * 3072;     // three 1024-float stages

    const float invL  = 1.0f / (float)L_DIM;
    const float invN1 = 1.0f / (float)(L_DIM - 1);

    // Running source pointers: chunk j has tensor=(j&1), row=c0/2 + j/2.
    const float4* pA = (const float4*)(a1 + (long long)(c0 >> 1) * L_DIM) + lane;
    const float4* pB = (const float4*)(a2 + (long long)(c0 >> 1) * L_DIM) + lane;
    int issue_stage = 0;                 // stage for next issued chunk

    // Issue next chunk (parity selects tensor); advances pointer + stage.
    #define ISSUE_NEXT(jpar_)                                                   \
    do {                                                                        \
        const float4* s4_;                                                      \
        if (jpar_ & 1) { s4_ = pB; pB += 256; }  /* 256 float4 = 1024 floats */ \
        else           { s4_ = pA; pA += 256; }                                 \
        float4* d4_ = (float4*)(stg + issue_stage * 1024) + lane;               \
        _Pragma("unroll")                                                       \
        for (int k_ = 0; k_ < 8; k_++)                                          \
            __pipeline_memcpy_async(&d4_[32 * k_], &s4_[32 * k_], 16);          \
        if (++issue_stage == 3) issue_stage = 0;                                \
    } while (0)

    // Prologue: chunks 0 and 1 in flight.
    if (n > 0) { ISSUE_NEXT(0); }
    __pipeline_commit();
    if (n > 1) { ISSUE_NEXT(1); }
    __pipeline_commit();

    int cons_stage = 0;                  // stage of chunk being consumed

    for (int i = 0; i < n; i++) {
        // Issue chunk i+2 (or empty commit) BEFORE waiting: keeps 2 in flight.
        if (i + 2 < n) { ISSUE_NEXT(i + 2); }
        __pipeline_commit();             // always commit -> constant wait count
        __pipeline_wait_prior(2);        // chunk i ready; i+1, i+2 in flight

        // ---- consume chunk i: row stats ----
        {
            const float4* d4 = (const float4*)(stg + cons_stage * 1024) + lane;
            float sa = 0.f, sb = 0.f, qa = 0.f, qb = 0.f;
            float mx = -FLT_MAX, mn = FLT_MAX;
            #pragma unroll
            for (int k = 0; k < 8; k++) {
                float4 v = d4[32 * k];
                if (k & 1) { sb += (v.x + v.y) + (v.z + v.w);
                             qb += (v.x * v.x + v.y * v.y) + (v.z * v.z + v.w * v.w); }
                else       { sa += (v.x + v.y) + (v.z + v.w);
                             qa += (v.x * v.x + v.y * v.y) + (v.z * v.z + v.w * v.w); }
                mx = fmaxf(mx, fmaxf(fmaxf(v.x, v.y), fmaxf(v.z, v.w)));
                mn = fminf(mn, fminf(fminf(v.x, v.y), fminf(v.z, v.w)));
            }
            if (++cons_stage == 3) cons_stage = 0;

            float s = sa + sb, q = qa + qb;
            #pragma unroll
            for (int off = 16; off > 0; off >>= 1) {
                s  += __shfl_xor_sync(0xffffffffu, s, off);
                q  += __shfl_xor_sync(0xffffffffu, q, off);
                mx  = fmaxf(mx, __shfl_xor_sync(0xffffffffu, mx, off));
                mn  = fminf(mn, __shfl_xor_sync(0xffffffffu, mn, off));
            }
            if (lane == 0) {
                const int lr = (i >> 1) & 7;      // local row in group (c0 even)
                const int t  = (i & 1) * 4;
                rs[w][lr * 8 + t + 0] = s;
                rs[w][lr * 8 + t + 1] = sqrtf(fmaxf(0.f, (q - s * s * invL) * invN1));
                rs[w][lr * 8 + t + 2] = mx;
                rs[w][lr * 8 + t + 3] = mn;
            }
        }

        // ---- group complete? inline MLP (2 chunks still in flight) ----
        if ((i & 15) == 15) {
            __syncwarp();
            const long long row0 = (long long)(g0 + (i >> 4)) * 8;

            float acc = 0.f;
            #pragma unroll
            for (int wi = 0; wi < 7; wi++) {
                int s, ws, r0;
                float wgt;
                if (wi == 0)      { s = 2; ws = 8; r0 = 0;            wgt = w2g; }
                else if (wi < 3)  { s = 1; ws = 4; r0 = (wi - 1) * 4; wgt = w1g; }
                else              { s = 0; ws = 2; r0 = (wi - 3) * 2; wgt = w0;  }

                const float invws = 1.0f / (float)ws;

                float g[8];
                {
                    float sm1 = 0.f, sd1 = 0.f, sx1 = 0.f, sn1 = 0.f;
                    float sm2 = 0.f, sd2 = 0.f, sx2 = 0.f, sn2 = 0.f;
                    #pragma unroll
                    for (int r = 0; r < 8; r++) {
                        if (r >= r0 && r < r0 + ws) {
                            sm1 += rs[w][r * 8 + 0]; sd1 += rs[w][r * 8 + 1];
                            sx1 += rs[w][r * 8 + 2]; sn1 += rs[w][r * 8 + 3];
                            sm2 += rs[w][r * 8 + 4]; sd2 += rs[w][r * 8 + 5];
                            sx2 += rs[w][r * 8 + 6]; sn2 += rs[w][r * 8 + 7];
                        }
                    }
                    g[0] = sm1 * invL * invws; g[1] = sd1 * invws;
                    g[2] = sx1 * invws;        g[3] = sn1 * invws;
                    g[4] = sm2 * invL * invws; g[5] = sd2 * invws;
                    g[6] = sx2 * invws;        g[7] = sn2 * invws;
                }

                // Layer 1: two 4-FMA chains
                float h1;
                {
                    float va = shB1[s][lane], vb = 0.f;
                    #pragma unroll
                    for (int f = 0; f < 4; f++) {
                        va = fmaf(shW1T[s][f][lane],     g[f],     va);
                        vb = fmaf(shW1T[s][f + 4][lane], g[f + 4], vb);
                    }
                    h1 = fmaxf(va + vb, 0.f);
                }
                // Layer 2: four 8-FMA chains (shfls independent, ILP)
                float h2;
                {
                    const int oo = lane & 15;
                    float v0 = shB2[s][oo], v1 = 0.f, v2 = 0.f, v3 = 0.f;
                    #pragma unroll
                    for (int f = 0; f < 8; f++) {
                        v0 = fmaf(shW2T[s][f][oo],      __shfl_sync(0xffffffffu, h1, f),      v0);
                        v1 = fmaf(shW2T[s][f + 8][oo],  __shfl_sync(0xffffffffu, h1, f + 8),  v1);
                        v2 = fmaf(shW2T[s][f + 16][oo], __shfl_sync(0xffffffffu, h1, f + 16), v2);
                        v3 = fmaf(shW2T[s][f + 24][oo], __shfl_sync(0xffffffffu, h1, f + 24), v3);
                    }
                    h2 = fmaxf((v0 + v1) + (v2 + v3), 0.f);
                }
                {
                    float part = (lane < 16) ? shW3[s][lane] * h2 : 0.f;
                    #pragma unroll
                    for (int off = 16; off > 0; off >>= 1)
                        part += __shfl_xor_sync(0xffffffffu, part, off);
                    float z = __shfl_sync(0xffffffffu, part, 0) + shB3[s];
                    float alpha = 1.0f / (1.0f + __expf(-z));
                    if (lane >= r0 && lane < r0 + ws)
                        acc = fmaf(wgt, alpha, acc);
                }
            }

            if (lane < 8)
                out[row0 + lane] = acc;
        }
    }
    #undef ISSUE_NEXT
}

extern "C" void kernel_launch(void* const* d_in, const int* in_sizes, int n_in,
                              void* d_out, int out_size) {
    const float* a1 = (const float*)d_in[0];
    const float* a2 = (const float*)d_in[1];
    const float* W1 = (const float*)d_in[2];
    const float* b1 = (const float*)d_in[3];
    const float* W2 = (const float*)d_in[4];
    const float* b2 = (const float*)d_in[5];
    const float* W3 = (const float*)d_in[6];
    const float* b3 = (const float*)d_in[7];
    const float* sw = (const float*)d_in[8];
    float* out = (float*)d_out;

    const int dyn_smem = 8 * 3 * 1024 * (int)sizeof(float);   // 96KB
    cudaFuncSetAttribute(msdfg_kernel,
                         cudaFuncAttributeMaxDynamicSharedMemorySize, dyn_smem);

    msdfg_kernel<<<GRID_A, 256, dyn_smem>>>(a1, a2, W1, b1, W2, b2, W3, b3, sw, out);
}

// round 14
// speedup vs baseline: 1.4767x; 1.4767x over previous
#include <cuda_runtime.h>
#include <cuda_pipeline.h>
#include <math.h>
#include <float.h>

// MultiScaleDynamicFusionGate — GB300 sm_103a — R14
//  A) stats kernel = R9's proven 83.5us streamer (296 blocks single wave,
//     balanced row partition, 2-stage cp.async), now row-ordered per tensor
//     (all a1 rows then a2 rows per warp) and zeroing `out` for B's atomics.
//  B) gate kernel: LANE-parallel windows — one lane = one window, scalar
//     MLP in registers, weights broadcast from shared (warp = one scale).
//     1792 warps, ~1.7K independent instrs each -> issue-bound ~4-6us
//     (vs 29us for R9's warp-per-group serial 7-window loop).
//     Frames combined via atomicAdd (RED.F32) of wgt*alpha per scale.

#define L_DIM 1024
#define N_ROWS 65536            // B*H*L
#define GRID_A 296
#define WARPS_A (GRID_A * 8)    // 2368

#define GRID_B 224              // 1792 warps: 1024 ws2 + 512 ws4 + 256 ws8

__device__ __align__(16) float g_stats[N_ROWS * 8]; // [row][s1,std1,mx1,mn1,s2,std2,mx2,mn2]

extern __shared__ float stageA[];       // [8 warps][2 stages][1024 floats] = 64KB

// ---------------------------------------------------------------- Kernel A
__global__ __launch_bounds__(256) void stats_kernel(
    const float* __restrict__ a1, const float* __restrict__ a2,
    float* __restrict__ out)
{
    const int w    = threadIdx.x >> 5;
    const int lane = threadIdx.x & 31;

    // Zero the output (gate kernel accumulates with atomics).
    {
        int idx = blockIdx.x * 256 + threadIdx.x;
        if (idx < N_ROWS) out[idx] = 0.f;
    }

    const long long gw = (long long)blockIdx.x * 8 + w;          // 0..2367
    const int r0 = (int)(((long long)N_ROWS * gw)       / WARPS_A);
    const int r1 = (int)(((long long)N_ROWS * (gw + 1)) / WARPS_A);
    const int nr = r1 - r0;             // 27 or 28 rows
    const int n  = nr * 2;              // chunks: nr of a1, then nr of a2

    float* stg = stageA + w * 2048;     // two 1024-float stages

    const float invL  = 1.0f / (float)L_DIM;
    const float invN1 = 1.0f / (float)(L_DIM - 1);

    // chunk i: tensor = (i < nr ? a1 : a2), row = r0 + (i % nr)
    #define ISSUE_CHUNK(i_)                                                     \
    do {                                                                        \
        int i2_ = (i_);                                                         \
        const float* base_ = (i2_ < nr) ? a1 : a2;                              \
        int row_ = r0 + ((i2_ < nr) ? i2_ : i2_ - nr);                          \
        const float4* s4_ = (const float4*)(base_ + (long long)row_ * L_DIM) + lane; \
        float4* d4_ = (float4*)(stg + (i2_ & 1) * 1024) + lane;                 \
        _Pragma("unroll")                                                       \
        for (int k_ = 0; k_ < 8; k_++)                                          \
            __pipeline_memcpy_async(&d4_[32 * k_], &s4_[32 * k_], 16);          \
    } while (0)

    if (n > 0) { ISSUE_CHUNK(0); }
    __pipeline_commit();

    for (int i = 0; i < n; i++) {
        if (i + 1 < n) { ISSUE_CHUNK(i + 1); }
        __pipeline_commit();            // always commit -> constant wait count
        __pipeline_wait_prior(1);       // chunk i complete; i+1 in flight

        const float4* d4 = (const float4*)(stg + (i & 1) * 1024) + lane;
        float sa = 0.f, sb = 0.f, qa = 0.f, qb = 0.f;
        float mx = -FLT_MAX, mn = FLT_MAX;
        #pragma unroll
        for (int k = 0; k < 8; k++) {
            float4 v = d4[32 * k];
            if (k & 1) { sb += (v.x + v.y) + (v.z + v.w);
                         qb += (v.x * v.x + v.y * v.y) + (v.z * v.z + v.w * v.w); }
            else       { sa += (v.x + v.y) + (v.z + v.w);
                         qa += (v.x * v.x + v.y * v.y) + (v.z * v.z + v.w * v.w); }
            mx = fmaxf(mx, fmaxf(fmaxf(v.x, v.y), fmaxf(v.z, v.w)));
            mn = fminf(mn, fminf(fminf(v.x, v.y), fminf(v.z, v.w)));
        }

        float s = sa + sb, q = qa + qb;
        #pragma unroll
        for (int off = 16; off > 0; off >>= 1) {
            s  += __shfl_xor_sync(0xffffffffu, s, off);
            q  += __shfl_xor_sync(0xffffffffu, q, off);
            mx  = fmaxf(mx, __shfl_xor_sync(0xffffffffu, mx, off));
            mn  = fminf(mn, __shfl_xor_sync(0xffffffffu, mn, off));
        }
        if (lane == 0) {
            int row = r0 + ((i < nr) ? i : i - nr);
            int t   = (i < nr) ? 0 : 4;
            float sd = sqrtf(fmaxf(0.f, (q - s * s * invL) * invN1));
            float4 st = make_float4(s, sd, mx, mn);
            *(float4*)(g_stats + (long long)row * 8 + t) = st;
        }
    }
    #undef ISSUE_CHUNK
}

// ---------------------------------------------------------------- Kernel B
__global__ __launch_bounds__(256) void gate_kernel(
    const float* __restrict__ W1, const float* __restrict__ b1,
    const float* __restrict__ W2, const float* __restrict__ b2,
    const float* __restrict__ W3, const float* __restrict__ b3,
    const float* __restrict__ sw, float* __restrict__ out)
{
    // Original (row-major) layouts: scalar per-lane MLP reads are warp-uniform
    // broadcasts from shared.
    __shared__ float shW1[3][32][8];
    __shared__ float shB1[3][32];
    __shared__ float shW2[3][16][32];
    __shared__ float shB2[3][16];
    __shared__ float shW3[3][16];
    __shared__ float shB3[3];
    __shared__ float shSW[3];

    const int tid  = threadIdx.x;
    const int w    = tid >> 5;
    const int lane = tid & 31;

    for (int idx = tid; idx < 768; idx += 256)  ((float*)shW1)[idx] = W1[idx];
    for (int idx = tid; idx < 1536; idx += 256) ((float*)shW2)[idx] = W2[idx];
    if (tid < 96)                 ((float*)shB1)[tid] = b1[tid];
    else if (tid < 144)           ((float*)shB2)[tid - 96]  = b2[tid - 96];
    else if (tid < 192)           ((float*)shW3)[tid - 144] = W3[tid - 144];
    else if (tid < 195)           ((float*)shB3)[tid - 192] = b3[tid - 192];
    else if (tid >= 200 && tid < 203) shSW[tid - 200] = sw[tid - 200];
    __syncthreads();

    // softmax(scale_weights)
    float wgt0, wgt1, wgt2;
    {
        float t0 = shSW[0], t1 = shSW[1], t2 = shSW[2];
        float m  = fmaxf(t0, fmaxf(t1, t2));
        float e0 = __expf(t0 - m), e1 = __expf(t1 - m), e2 = __expf(t2 - m);
        float inv = 1.0f / (e0 + e1 + e2);
        wgt0 = e0 * inv; wgt1 = e1 * inv; wgt2 = e2 * inv;  // ws=2,4,8
    }

    const int gw = blockIdx.x * 8 + w;   // 0..1791
    int s, ws, win;
    float wgt;
    if (gw < 1024)      { s = 0; ws = 2; win = gw * 32 + lane;          wgt = wgt0; }
    else if (gw < 1536) { s = 1; ws = 4; win = (gw - 1024) * 32 + lane; wgt = wgt1; }
    else                { s = 2; ws = 8; win = (gw - 1536) * 32 + lane; wgt = wgt2; }

    const long long rowb = (long long)win * ws;
    const float invL  = 1.0f / (float)L_DIM;
    const float invws = 1.0f / (float)ws;

    // Accumulate window features from per-row stats (L2-hot).
    float a0 = 0.f, a1v = 0.f, a2v = 0.f, a3 = 0.f;
    float a4 = 0.f, a5 = 0.f, a6 = 0.f, a7 = 0.f;
    for (int r = 0; r < ws; r++) {
        const float4* p = (const float4*)(g_stats + (rowb + r) * 8);
        float4 x = p[0], y = p[1];
        a0 += x.x; a1v += x.y; a2v += x.z; a3 += x.w;
        a4 += y.x; a5  += y.y; a6  += y.z; a7 += y.w;
    }
    float g[8];
    g[0] = a0 * invL * invws; g[1] = a1v * invws;
    g[2] = a2v * invws;       g[3] = a3 * invws;
    g[4] = a4 * invL * invws; g[5] = a5 * invws;
    g[6] = a6 * invws;        g[7] = a7 * invws;

    // Scalar MLP per lane (weights are warp-uniform broadcasts).
    float h1[32];
    #pragma unroll
    for (int o = 0; o < 32; o++) {
        float v = shB1[s][o];
        #pragma unroll
        for (int f = 0; f < 8; f++) v = fmaf(shW1[s][o][f], g[f], v);
        h1[o] = fmaxf(v, 0.f);
    }
    float h2[16];
    #pragma unroll
    for (int o = 0; o < 16; o++) {
        float v = shB2[s][o];
        #pragma unroll
        for (int f = 0; f < 32; f++) v = fmaf(shW2[s][o][f], h1[f], v);
        h2[o] = fmaxf(v, 0.f);
    }
    float z = shB3[s];
    #pragma unroll
    for (int f = 0; f < 16; f++) z = fmaf(shW3[s][f], h2[f], z);

    float alpha = 1.0f / (1.0f + __expf(-z));
    float val = wgt * alpha;

    for (int r = 0; r < ws; r++)
        atomicAdd(&out[rowb + r], val);
}

extern "C" void kernel_launch(void* const* d_in, const int* in_sizes, int n_in,
                              void* d_out, int out_size) {
    const float* a1 = (const float*)d_in[0];
    const float* a2 = (const float*)d_in[1];
    const float* W1 = (const float*)d_in[2];
    const float* b1 = (const float*)d_in[3];
    const float* W2 = (const float*)d_in[4];
    const float* b2 = (const float*)d_in[5];
    const float* W3 = (const float*)d_in[6];
    const float* b3 = (const float*)d_in[7];
    const float* sw = (const float*)d_in[8];
    float* out = (float*)d_out;

    const int dyn_smem = 8 * 2 * 1024 * (int)sizeof(float);   // 64KB
    cudaFuncSetAttribute(stats_kernel,
                         cudaFuncAttributeMaxDynamicSharedMemorySize, dyn_smem);

    stats_kernel<<<GRID_A, 256, dyn_smem>>>(a1, a2, out);
    gate_kernel<<<GRID_B, 256>>>(W1, b1, W2, b2, W3, b3, sw, out);
}